// round 10
// baseline (speedup 1.0000x reference)
#include <cuda_runtime.h>

#define SCALE 0.125f

// ---------------- scratch (device globals: allocation-free) ----------------
__device__ float g_ep[134217728];    // exp(SCALE*q.k)  (2,16,2048,2048) 536.9 MB
__device__ float g_qkv[12582912];    // (2,2048,3072)  50.3 MB
__device__ float g_zinv[8388608];    // (2,2048,2048)  33.5 MB
__device__ float g_wavg[4194304];    // (2,2048,1024)  16.8 MB

// ---------------- f32x2 packed-FMA helper ----------------
__device__ __forceinline__ void fma2(unsigned long long& c, unsigned long long a, unsigned long long b) {
    asm("fma.rn.f32x2 %0, %1, %2, %3;" : "=l"(c) : "l"(a), "l"(b), "l"(c));
}
__device__ __forceinline__ float2 unpack2(unsigned long long v) {
    float2 r;
    asm("mov.b64 {%0, %1}, %2;" : "=f"(r.x), "=f"(r.y) : "l"(v));
    return r;
}

// ---------------- FMA-pipe exp (no MUFU) ----------------
__device__ __forceinline__ float fexp(float x) {
    float t = x * 1.44269504088896340736f;
    float i = rintf(t);
    float y = fmaf(-i, 0.69314718055994530942f, x);
    float p = 8.3333337680e-3f;                        // 1/120
    p = fmaf(p, y, 4.1666668654e-2f);                  // 1/24
    p = fmaf(p, y, 1.6666667163e-1f);                  // 1/6
    p = fmaf(p, y, 5.0000000000e-1f);
    p = fmaf(p, y, 1.0f);
    p = fmaf(p, y, 1.0f);
    return __int_as_float(__float_as_int(p) + (((int)i) << 23));
}

// ======================================================================
// Generic NN GEMM with bias, 2-stage pipelined, mov-free operand paths.
// C[M,N] = A[M,K] @ B[K,N] + bias[N]
// BM=128, BN=128, BK=8, 256 threads, 8x8 microtile via f32x2, occ 2.
// A stored DUPLICATED in smem ([a,a] pairs); B pairs read as ulonglong2.
// ======================================================================
__global__ __launch_bounds__(256, 2)
void gemm_nn_bias(const float* __restrict__ A, const float* __restrict__ Bm,
                  const float* __restrict__ bias, float* __restrict__ C,
                  int M, int N, int K)
{
    __shared__ float As2[2][8][260];   // [k][2*m] duplicated, pad 260
    __shared__ float Bs[2][8][132];    // [k][n], pad 132
    const int tid = threadIdx.x;
    const int bm = blockIdx.y << 7;
    const int bn = blockIdx.x << 7;
    const int tx = tid & 15, ty = tid >> 4;

    const int arow  = tid >> 1, akseg = (tid & 1) * 4;   // A fill: 1 float4/thread
    const int brow  = tid >> 5, bcol  = (tid & 31) << 2; // B fill: 1 float4/thread

    unsigned long long acc[8][4];
#pragma unroll
    for (int i = 0; i < 8; i++)
#pragma unroll
        for (int j = 0; j < 4; j++) acc[i][j] = 0ull;

    const float* Ab = A + (size_t)bm * K;
    const float* Bb = Bm + bn;

    // ---- prologue: tile 0 ----
    {
        float4 va = *(const float4*)(Ab + (size_t)arow * K + akseg);
        float4 vb = *(const float4*)(Bb + (size_t)brow * N + bcol);
        *(float2*)&As2[0][akseg+0][arow*2] = make_float2(va.x, va.x);
        *(float2*)&As2[0][akseg+1][arow*2] = make_float2(va.y, va.y);
        *(float2*)&As2[0][akseg+2][arow*2] = make_float2(va.z, va.z);
        *(float2*)&As2[0][akseg+3][arow*2] = make_float2(va.w, va.w);
        *(float4*)&Bs[0][brow][bcol] = vb;
    }
    __syncthreads();

    int cur = 0;
    for (int k0 = 0; k0 < K; k0 += 8) {
        const bool has_next = (k0 + 8) < K;
        float4 va, vb;
        if (has_next) {
            va = *(const float4*)(Ab + (size_t)arow * K + (k0 + 8) + akseg);
            vb = *(const float4*)(Bb + (size_t)(k0 + 8 + brow) * N + bcol);
        }
#pragma unroll
        for (int kk = 0; kk < 8; kk++) {
            const float* a2 = &As2[cur][kk][ty*16];
            ulonglong2 aA = *(const ulonglong2*)(a2);       // (m0,m0),(m1,m1)
            ulonglong2 aB = *(const ulonglong2*)(a2 + 4);
            ulonglong2 aC = *(const ulonglong2*)(a2 + 8);
            ulonglong2 aD = *(const ulonglong2*)(a2 + 12);
            ulonglong2 b01 = *(const ulonglong2*)&Bs[cur][kk][tx*8];     // (n0,n1),(n2,n3)
            ulonglong2 b23 = *(const ulonglong2*)&Bs[cur][kk][tx*8 + 4];
            unsigned long long ap[8] = {aA.x,aA.y,aB.x,aB.y,aC.x,aC.y,aD.x,aD.y};
            unsigned long long bp[4] = {b01.x,b01.y,b23.x,b23.y};
#pragma unroll
            for (int i = 0; i < 8; i++)
#pragma unroll
                for (int j = 0; j < 4; j++) fma2(acc[i][j], ap[i], bp[j]);
        }
        if (has_next) {
            int nxt = cur ^ 1;
            *(float2*)&As2[nxt][akseg+0][arow*2] = make_float2(va.x, va.x);
            *(float2*)&As2[nxt][akseg+1][arow*2] = make_float2(va.y, va.y);
            *(float2*)&As2[nxt][akseg+2][arow*2] = make_float2(va.z, va.z);
            *(float2*)&As2[nxt][akseg+3][arow*2] = make_float2(va.w, va.w);
            *(float4*)&Bs[nxt][brow][bcol] = vb;
        }
        __syncthreads();
        cur ^= 1;
    }
#pragma unroll
    for (int i = 0; i < 8; i++) {
        int row = bm + ty*8 + i;
#pragma unroll
        for (int j = 0; j < 4; j++) {
            float2 v = unpack2(acc[i][j]);
            int col = bn + tx*8 + j*2;
            float2 o = make_float2(v.x + bias[col], v.y + bias[col+1]);
            *(float2*)&C[(size_t)row * N + col] = o;
        }
    }
}

// ======================================================================
// Batched NT GEMM + fused FMA-pipe exp epilogue, pipelined, mov-free:
// ep[z][q][k] = exp(SCALE * Q_z[q,:] . K_z[k,:])   (Kdim=64), BK=8.
// ======================================================================
__global__ __launch_bounds__(256, 2)
void gemm_qk_exp(const float* __restrict__ qkv, float* __restrict__ ep)
{
    __shared__ float As2[2][8][260];   // duplicated Q
    __shared__ float Bs[2][8][132];    // K transposed: [k][n]
    const int tid = threadIdx.x;
    const int z = blockIdx.z;
    const int b = z >> 4, h = z & 15;
    const int bm = blockIdx.y << 7, bn = blockIdx.x << 7;
    const int tx = tid & 15, ty = tid >> 4;

    const float* Aq = qkv + (size_t)b * 6291456 + h * 64;           // Q
    const float* Bk = qkv + (size_t)b * 6291456 + 1024 + h * 64;    // K
    float* C = ep + (size_t)z * 4194304;

    const int row = tid >> 1, kseg = (tid & 1) * 4;   // both fills: 1 float4/thread

    unsigned long long acc[8][4];
#pragma unroll
    for (int i = 0; i < 8; i++)
#pragma unroll
        for (int j = 0; j < 4; j++) acc[i][j] = 0ull;

    // ---- prologue: tile 0 ----
    {
        float4 va = *(const float4*)(Aq + (size_t)(bm + row) * 3072 + kseg);
        float4 vb = *(const float4*)(Bk + (size_t)(bn + row) * 3072 + kseg);
        *(float2*)&As2[0][kseg+0][row*2] = make_float2(va.x, va.x);
        *(float2*)&As2[0][kseg+1][row*2] = make_float2(va.y, va.y);
        *(float2*)&As2[0][kseg+2][row*2] = make_float2(va.z, va.z);
        *(float2*)&As2[0][kseg+3][row*2] = make_float2(va.w, va.w);
        Bs[0][kseg+0][row] = vb.x;
        Bs[0][kseg+1][row] = vb.y;
        Bs[0][kseg+2][row] = vb.z;
        Bs[0][kseg+3][row] = vb.w;
    }
    __syncthreads();

    int cur = 0;
    for (int k0 = 0; k0 < 64; k0 += 8) {
        const bool has_next = (k0 + 8) < 64;
        float4 va, vb;
        if (has_next) {
            int kn = k0 + 8;
            va = *(const float4*)(Aq + (size_t)(bm + row) * 3072 + kn + kseg);
            vb = *(const float4*)(Bk + (size_t)(bn + row) * 3072 + kn + kseg);
        }
#pragma unroll
        for (int kk = 0; kk < 8; kk++) {
            const float* a2 = &As2[cur][kk][ty*16];
            ulonglong2 aA = *(const ulonglong2*)(a2);
            ulonglong2 aB = *(const ulonglong2*)(a2 + 4);
            ulonglong2 aC = *(const ulonglong2*)(a2 + 8);
            ulonglong2 aD = *(const ulonglong2*)(a2 + 12);
            ulonglong2 b01 = *(const ulonglong2*)&Bs[cur][kk][tx*8];
            ulonglong2 b23 = *(const ulonglong2*)&Bs[cur][kk][tx*8 + 4];
            unsigned long long ap[8] = {aA.x,aA.y,aB.x,aB.y,aC.x,aC.y,aD.x,aD.y};
            unsigned long long bp[4] = {b01.x,b01.y,b23.x,b23.y};
#pragma unroll
            for (int i = 0; i < 8; i++)
#pragma unroll
                for (int j = 0; j < 4; j++) fma2(acc[i][j], ap[i], bp[j]);
        }
        if (has_next) {
            int nxt = cur ^ 1;
            *(float2*)&As2[nxt][kseg+0][row*2] = make_float2(va.x, va.x);
            *(float2*)&As2[nxt][kseg+1][row*2] = make_float2(va.y, va.y);
            *(float2*)&As2[nxt][kseg+2][row*2] = make_float2(va.z, va.z);
            *(float2*)&As2[nxt][kseg+3][row*2] = make_float2(va.w, va.w);
            Bs[nxt][kseg+0][row] = vb.x;
            Bs[nxt][kseg+1][row] = vb.y;
            Bs[nxt][kseg+2][row] = vb.z;
            Bs[nxt][kseg+3][row] = vb.w;
        }
        __syncthreads();
        cur ^= 1;
    }
#pragma unroll
    for (int i = 0; i < 8; i++) {
        int r = bm + ty*8 + i;
#pragma unroll
        for (int j = 0; j < 4; j++) {
            float2 v = unpack2(acc[i][j]);
            int col = bn + tx*8 + j*2;
            float2 o = make_float2(fexp(v.x * SCALE), fexp(v.y * SCALE));
            __stcs((float2*)&C[(size_t)r * 2048 + col], o);
        }
    }
}

// ======================================================================
// zinv[b,q,k] = 1 / sum_h ep[b,h,q,k]   (softmax over HEADS axis)
// ======================================================================
__global__ __launch_bounds__(256)
void softmax_z(const float* __restrict__ ep, float* __restrict__ zinv)
{
    size_t i4 = (size_t)blockIdx.x * 256 + threadIdx.x;  // over 2*2048*2048/4
    size_t b = i4 >> 20;
    size_t qk4 = i4 & 1048575;
    const float4* p = (const float4*)(ep + (b << 26)) + qk4;
    float4 s = make_float4(0.f, 0.f, 0.f, 0.f);
#pragma unroll
    for (int h = 0; h < 16; h++) {
        float4 v = __ldcs(p + ((size_t)h << 20));
        s.x += v.x; s.y += v.y; s.z += v.z; s.w += v.w;
    }
    float4 o = make_float4(1.f/s.x, 1.f/s.y, 1.f/s.z, 1.f/s.w);
    *((float4*)zinv + i4) = o;
}

// ======================================================================
// Batched NN GEMM with normalization on A, pipelined, mov-free:
// wavg[b,q,h*64+d] = sum_k (ep[z,q,k]*zinv[b,q,k]) * V[b,k,h,d]
// BM=128, BN=64, BK=16, 256 threads, 8x4 microtile.
// ======================================================================
__global__ __launch_bounds__(256, 2)
void gemm_pv(const float* __restrict__ ep, const float* __restrict__ zinv,
             const float* __restrict__ qkv, float* __restrict__ wavg)
{
    __shared__ float As2[2][16][260];  // duplicated attn
    __shared__ float Bs[2][16][72];    // V tile, pad 72
    const int tid = threadIdx.x;
    const int z = blockIdx.z, b = z >> 4, h = z & 15;
    const int bm = blockIdx.y << 7;
    const int tx = tid & 15, ty = tid >> 4;

    const float* A  = ep + (size_t)z * 4194304 + (size_t)bm * 2048;
    const float* Zi = zinv + (size_t)b * 4194304 + (size_t)bm * 2048;
    const float* Bv = qkv + (size_t)b * 6291456 + 2048 + h * 64;
    float* C = wavg + (size_t)b * 2097152 + h * 64;

    const int row0 = tid >> 2,          seg0 = tid & 3;
    const int row1 = (tid + 256) >> 2,  seg1 = tid & 3;
    const int vr = tid >> 4, vc = (tid & 15) << 2;

    unsigned long long acc[8][2];
#pragma unroll
    for (int i = 0; i < 8; i++) { acc[i][0] = 0ull; acc[i][1] = 0ull; }

    // ---- prologue: tile 0 ----
    {
        size_t o0 = (size_t)row0 * 2048 + seg0 * 4;
        size_t o1 = (size_t)row1 * 2048 + seg1 * 4;
        float4 a0 = __ldcs((const float4*)(A + o0));
        float4 a1 = __ldcs((const float4*)(A + o1));
        float4 z0 = *(const float4*)(Zi + o0);
        float4 z1 = *(const float4*)(Zi + o1);
        float4 vv = *(const float4*)(Bv + (size_t)vr * 3072 + vc);
        float p0;
        p0 = a0.x*z0.x; *(float2*)&As2[0][seg0*4+0][row0*2] = make_float2(p0,p0);
        p0 = a0.y*z0.y; *(float2*)&As2[0][seg0*4+1][row0*2] = make_float2(p0,p0);
        p0 = a0.z*z0.z; *(float2*)&As2[0][seg0*4+2][row0*2] = make_float2(p0,p0);
        p0 = a0.w*z0.w; *(float2*)&As2[0][seg0*4+3][row0*2] = make_float2(p0,p0);
        p0 = a1.x*z1.x; *(float2*)&As2[0][seg1*4+0][row1*2] = make_float2(p0,p0);
        p0 = a1.y*z1.y; *(float2*)&As2[0][seg1*4+1][row1*2] = make_float2(p0,p0);
        p0 = a1.z*z1.z; *(float2*)&As2[0][seg1*4+2][row1*2] = make_float2(p0,p0);
        p0 = a1.w*z1.w; *(float2*)&As2[0][seg1*4+3][row1*2] = make_float2(p0,p0);
        *(float4*)&Bs[0][vr][vc] = vv;
    }
    __syncthreads();

    int cur = 0;
    for (int k0 = 0; k0 < 2048; k0 += 16) {
        const bool has_next = (k0 + 16) < 2048;
        float4 a0, a1, z0, z1, vv;
        if (has_next) {
            int kn = k0 + 16;
            size_t o0 = (size_t)row0 * 2048 + kn + seg0 * 4;
            size_t o1 = (size_t)row1 * 2048 + kn + seg1 * 4;
            a0 = __ldcs((const float4*)(A + o0));
            a1 = __ldcs((const float4*)(A + o1));
            z0 = *(const float4*)(Zi + o0);
            z1 = *(const float4*)(Zi + o1);
            vv = *(const float4*)(Bv + (size_t)(kn + vr) * 3072 + vc);
        }
#pragma unroll
        for (int kk = 0; kk < 16; kk++) {
            const float* a2 = &As2[cur][kk][ty*16];
            ulonglong2 aA = *(const ulonglong2*)(a2);
            ulonglong2 aB = *(const ulonglong2*)(a2 + 4);
            ulonglong2 aC = *(const ulonglong2*)(a2 + 8);
            ulonglong2 aD = *(const ulonglong2*)(a2 + 12);
            ulonglong2 bb = *(const ulonglong2*)&Bs[cur][kk][tx*4];
            unsigned long long ap[8] = {aA.x,aA.y,aB.x,aB.y,aC.x,aC.y,aD.x,aD.y};
#pragma unroll
            for (int i = 0; i < 8; i++) {
                fma2(acc[i][0], ap[i], bb.x);
                fma2(acc[i][1], ap[i], bb.y);
            }
        }
        if (has_next) {
            int nxt = cur ^ 1;
            float p0;
            p0 = a0.x*z0.x; *(float2*)&As2[nxt][seg0*4+0][row0*2] = make_float2(p0,p0);
            p0 = a0.y*z0.y; *(float2*)&As2[nxt][seg0*4+1][row0*2] = make_float2(p0,p0);
            p0 = a0.z*z0.z; *(float2*)&As2[nxt][seg0*4+2][row0*2] = make_float2(p0,p0);
            p0 = a0.w*z0.w; *(float2*)&As2[nxt][seg0*4+3][row0*2] = make_float2(p0,p0);
            p0 = a1.x*z1.x; *(float2*)&As2[nxt][seg1*4+0][row1*2] = make_float2(p0,p0);
            p0 = a1.y*z1.y; *(float2*)&As2[nxt][seg1*4+1][row1*2] = make_float2(p0,p0);
            p0 = a1.z*z1.z; *(float2*)&As2[nxt][seg1*4+2][row1*2] = make_float2(p0,p0);
            p0 = a1.w*z1.w; *(float2*)&As2[nxt][seg1*4+3][row1*2] = make_float2(p0,p0);
            *(float4*)&Bs[nxt][vr][vc] = vv;
        }
        __syncthreads();
        cur ^= 1;
    }
#pragma unroll
    for (int i = 0; i < 8; i++) {
        int r = bm + ty*8 + i;
#pragma unroll
        for (int j = 0; j < 2; j++) {
            float2 v = unpack2(acc[i][j]);
            *(float2*)&C[(size_t)r * 1024 + tx*4 + j*2] = v;
        }
    }
}

// ======================================================================
extern "C" void kernel_launch(void* const* d_in, const int* in_sizes, int n_in,
                              void* d_out, int out_size)
{
    const float* x      = (const float*)d_in[0];   // (2,2048,1024)
    const float* w_qkv  = (const float*)d_in[1];   // (1024,3072)
    const float* b_qkv  = (const float*)d_in[2];   // (3072,)
    const float* w_proj = (const float*)d_in[3];   // (1024,1024)
    const float* b_proj = (const float*)d_in[4];   // (1024,)
    float* out = (float*)d_out;                    // (2,2048,1024)

    float *qkv, *ep, *zinv, *wavg;
    cudaGetSymbolAddress((void**)&qkv,  g_qkv);
    cudaGetSymbolAddress((void**)&ep,   g_ep);
    cudaGetSymbolAddress((void**)&zinv, g_zinv);
    cudaGetSymbolAddress((void**)&wavg, g_wavg);

    // 1) qkv = x @ w_qkv + b_qkv          (M=4096, N=3072, K=1024)
    gemm_nn_bias<<<dim3(24, 32), 256>>>(x, w_qkv, b_qkv, qkv, 4096, 3072, 1024);
    // 2) ep[b,h,q,k] = exp(SCALE * q.k)   (32 batches of 2048x2048x64, FMA-exp fused)
    gemm_qk_exp<<<dim3(16, 16, 32), 256>>>(qkv, ep);
    // 3) zinv = 1 / sum_h ep              (softmax denominator over heads)
    softmax_z<<<8192, 256>>>(ep, zinv);
    // 4) wavg = (ep*zinv) @ V             (32 batches of 2048x64x2048)
    gemm_pv<<<dim3(1, 16, 32), 256>>>(ep, zinv, qkv, wavg);
    // 5) out = wavg @ w_proj + b_proj     (M=4096, N=1024, K=1024)
    gemm_nn_bias<<<dim3(8, 32), 256>>>(wavg, w_proj, b_proj, out, 4096, 1024, 1024);
}